// round 7
// baseline (speedup 1.0000x reference)
#include <cuda_runtime.h>
#include <math.h>

#define BATCH 64
#define N 256
#define NT 256
#define INF_F 1e30f
#define FULLM 0xffffffffu

// per-batch matched-distance sums (deterministic, no atomics)
__device__ float g_batch_sum[BATCH];

__device__ __forceinline__ float sqrt_approx(float x) {
    float r;
    asm("sqrt.approx.f32 %0, %1;" : "=f"(r) : "f"(x));
    return r;
}

__global__ void __launch_bounds__(NT, 1)
hungarian_kernel(const float* __restrict__ pred,
                 const float* __restrict__ target)
{
    const int b = blockIdx.x;
    const int t = threadIdx.x;
    const int lane = t & 31;

    __shared__ float4 spt[N];            // pred xyz; .w = row potential u
    __shared__ float4 stgt[N];           // target xyz; .w = initial col potential v
    __shared__ int    sp[N + 1];         // row matched to column j (1-based; 0=free)
    __shared__ short  sway[N + 1];       // predecessor column on path
    __shared__ short  sargr[N];          // argmin row per column
    __shared__ unsigned char srowm[N];   // row matched flag (prematch)
    __shared__ short  sunm[N];           // free rows for path phase
    __shared__ int    s_nunm;

    // ---- phase A: all 256 threads. load + column reduction ----
    const float* pb = pred   + (size_t)b * N * 3;
    const float* tb = target + (size_t)b * N * 3;
    spt[t] = make_float4(pb[t * 3], pb[t * 3 + 1], pb[t * 3 + 2], 0.0f);
    const float qx = tb[t * 3], qy = tb[t * 3 + 1], qz = tb[t * 3 + 2];
    sp[t] = 0;
    srowm[t] = 0;
    if (t == 0) sp[N] = 0;
    __syncthreads();

    {
        float bd2 = INF_F; int br = 0;
        #pragma unroll 4
        for (int r = 0; r < N; ++r) {
            const float4 p = spt[r];
            const float dx = p.x - qx, dy = p.y - qy, dz = p.z - qz;
            const float d2 = fmaf(dx, dx, fmaf(dy, dy, dz * dz));
            if (d2 < bd2) { bd2 = d2; br = r; }
        }
        sargr[t] = (short)br;
        stgt[t] = make_float4(qx, qy, qz, sqrt_approx(bd2));  // .w = v[j]
    }
    __syncthreads();

    // ---- greedy pre-match on tight edges (t0, serial) ----
    if (t == 0) {
        for (int jj = 1; jj <= N; ++jj) {
            const int r = sargr[jj - 1];
            if (!srowm[r]) { srowm[r] = 1; sp[jj] = r + 1; }
        }
        int cnt = 0;
        for (int r = 0; r < N; ++r)
            if (!srowm[r]) sunm[cnt++] = (short)(r + 1);
        s_nunm = cnt;
    }
    __syncthreads();

    if (t >= 32) return;    // ==== warp 0 only from here; no __syncthreads below ====

    const int nunm = s_nunm;
    float tx[8], ty[8], tz[8], v[8];
    #pragma unroll
    for (int k = 0; k < 8; ++k) {
        const float4 g = stgt[(lane << 3) + k];
        tx[k] = g.x; ty[k] = g.y; tz[k] = g.z; v[k] = g.w;
    }

    // ====== exact augmenting paths (Dijkstra, deferred dual updates) ======
    for (int ii = 0; ii < nunm; ++ii) {
        const int istart = sunm[ii];
        unsigned ekey[8];          // fmap(shortest[k]); 0xfffffff0 = INF (never reset)
        float    mshort[8];        // shortest value when column became used
        int      myrow[8];
        float    vv[8];            // working v; -INF marks used (cost -> +INF)
        unsigned usedm = 0;
        #pragma unroll
        for (int k = 0; k < 8; ++k) { ekey[k] = 0xfffffff0u; vv[k] = v[k]; }

        float minVal = 0.0f;
        int i0 = istart, j0 = 0;

        for (;;) {
            // mark column j0 used (owner lane only); ekey/sway stay frozen
            if (j0) {
                const int c0 = j0 - 1;
                if ((c0 >> 3) == lane) {
                    const int k = c0 & 7;
                    usedm |= 1u << k;
                    myrow[k]  = i0;
                    mshort[k] = minVal;
                    vv[k]     = -INF_F;
                }
            }

            const float4 p = spt[i0 - 1];        // xyz + u[i0], LDS.128 broadcast
            const float base = minVal - p.w;

            #pragma unroll
            for (int k = 0; k < 8; ++k) {
                const float dx = p.x - tx[k];
                const float dy = p.y - ty[k];
                const float dz = p.z - tz[k];
                const float s  = sqrt_approx(fmaf(dx, dx, fmaf(dy, dy, dz * dz)));
                const float cur = fmaxf((base - vv[k]) + s, 0.0f);  // used: +INF
                const unsigned ck = __float_as_uint(cur) | 0x80000000u;
                if (ck < ekey[k]) {                 // used cols: INF key never passes
                    ekey[k] = ck;
                    sway[(lane << 3) + k + 1] = (short)j0;
                }
            }

            // local argmin/min over FREE columns only (used masked to 0xffffffff)
            unsigned m = 0xffffffffu, e = 0xffffffffu;
            #pragma unroll
            for (int k = 0; k < 8; ++k) {
                const unsigned kk = ekey[k] | (0u - ((usedm >> k) & 1u));
                const unsigned pk = (kk & ~7u) | (unsigned)k;
                m = m < pk ? m : pk;
                e = e < kk ? e : kk;
            }

            const unsigned wp = __reduce_min_sync(FULLM, m);   // argmin (trunc key)
            const unsigned we = __reduce_min_sync(FULLM, e);   // exact min value
            const unsigned ball = __ballot_sync(FULLM, m == wp);
            const int wl = __ffs(ball) - 1;
            const int j1 = (wl << 3) + (int)(wp & 7u) + 1;
            minVal = __uint_as_float(we & 0x7fffffffu);        // funmap (non-neg)

            const int i0n = sp[j1];
            if (i0n == 0) {
                __syncwarp();                 // sway writes visible to lane 0
                #pragma unroll
                for (int k = 0; k < 8; ++k) {
                    if ((usedm >> k) & 1u) {
                        const float d = minVal - mshort[k];
                        v[k] -= d;
                        spt[myrow[k] - 1].w += d;   // distinct rows: no conflict
                    }
                }
                if (lane == 0) {
                    spt[istart - 1].w += minVal;
                    sp[0] = istart;           // terminus picks up the free row
                    int jj = j1;
                    while (jj) {
                        const int jn = sway[jj];
                        sp[jj] = sp[jn];
                        jj = jn;
                    }
                }
                __syncwarp();                 // sp/u updates visible to all lanes
                break;
            }
            j0 = j1;
            i0 = i0n;
        }
    }

    // ---- matched distances (exact sqrt), warp-reduce ----
    float md = 0.0f;
    #pragma unroll
    for (int k = 0; k < 8; ++k) {
        const int c = (lane << 3) + k;
        const int r = sp[c + 1] - 1;
        const float4 p = spt[r];
        const float dx = p.x - tx[k];
        const float dy = p.y - ty[k];
        const float dz = p.z - tz[k];
        md += sqrtf(fmaf(dx, dx, fmaf(dy, dy, dz * dz)));
    }
    #pragma unroll
    for (int o = 16; o > 0; o >>= 1)
        md += __shfl_down_sync(FULLM, md, o);
    if (lane == 0) g_batch_sum[b] = md;
}

__global__ void finalize_kernel(float* __restrict__ out)
{
    double s = 0.0;
    #pragma unroll
    for (int b = 0; b < BATCH; ++b) s += (double)g_batch_sum[b];
    out[0] = (float)(s / (double)BATCH);
}

extern "C" void kernel_launch(void* const* d_in, const int* in_sizes, int n_in,
                              void* d_out, int out_size)
{
    const float* pred   = (const float*)d_in[0];
    const float* target = (const float*)d_in[1];
    float* out = (float*)d_out;

    hungarian_kernel<<<BATCH, NT>>>(pred, target);
    finalize_kernel<<<1, 1>>>(out);
}

// round 8
// speedup vs baseline: 1.4820x; 1.4820x over previous
#include <cuda_runtime.h>
#include <math.h>

#define BATCH 64
#define N 256
#define NT 256
#define INF_F 1e30f
#define FULLM 0xffffffffu

// per-batch matched-distance sums (deterministic, no atomics)
__device__ float g_batch_sum[BATCH];

__device__ __forceinline__ float sqrt_approx(float x) {
    float r;
    asm("sqrt.approx.f32 %0, %1;" : "=f"(r) : "f"(x));
    return r;
}

__global__ void __launch_bounds__(NT, 1)
hungarian_kernel(const float* __restrict__ pred,
                 const float* __restrict__ target)
{
    const int b = blockIdx.x;
    const int t = threadIdx.x;      // thread t owns column j = t+1 (1-based)
    const int lane = t & 31;
    const int w = t >> 5;
    const int j = t + 1;

    __shared__ float4 spt[N];                 // pred xyz; .w = row potential u
    __shared__ int    sp[N + 1];              // row matched to col j (1-based; 0=free)
    __shared__ short  sway[N + 1];            // predecessor column on path
    __shared__ short  sargr[N];               // argmin row per column
    __shared__ unsigned char srowm[N];        // row matched flag (prematch)
    __shared__ short  sunm[N];                // free rows for path phase
    __shared__ int    s_nunm;
    __shared__ __align__(16) unsigned long long rbuf[2][8];  // (exactmin<<32)|col
    __shared__ float  fsum[8];

    // ---- load points ----
    const float* pb = pred   + (size_t)b * N * 3;
    const float* tb = target + (size_t)b * N * 3;
    spt[t] = make_float4(pb[t * 3], pb[t * 3 + 1], pb[t * 3 + 2], 0.0f);
    const float tx = tb[t * 3], ty = tb[t * 3 + 1], tz = tb[t * 3 + 2];
    sp[t] = 0;
    srowm[t] = 0;
    if (t == 0) sp[N] = 0;
    __syncthreads();

    // ---- column reduction on SQUARED distance (sqrt monotonic) ----
    float v;
    {
        float bd2 = INF_F; int br = 0;
        #pragma unroll 4
        for (int r = 0; r < N; ++r) {
            const float4 p = spt[r];
            const float dx = p.x - tx, dy = p.y - ty, dz = p.z - tz;
            const float d2 = fmaf(dx, dx, fmaf(dy, dy, dz * dz));
            if (d2 < bd2) { bd2 = d2; br = r; }
        }
        sargr[t] = (short)br;
        v = sqrt_approx(bd2);
    }
    __syncthreads();

    // ---- greedy pre-match on tight edges (t0, serial) ----
    if (t == 0) {
        for (int jj = 1; jj <= N; ++jj) {
            const int r = sargr[jj - 1];
            if (!srowm[r]) { srowm[r] = 1; sp[jj] = r + 1; }
        }
        int cnt = 0;
        for (int r = 0; r < N; ++r)
            if (!srowm[r]) sunm[cnt++] = (short)(r + 1);
        s_nunm = cnt;
    }
    __syncthreads();
    const int nunm = s_nunm;

    // ====== exact augmenting paths (Dijkstra, deferred dual updates) ======
    for (int ii = 0; ii < nunm; ++ii) {
        const int istart = sunm[ii];
        unsigned ekey  = 0xfffffff0u;   // fmap(shortest); frozen once used
        unsigned usedf = 0u;
        float    vv = v;                // -INF marks used (cost -> +INF, no updates)
        float    mshort = 0.0f;
        int      myrow = 0;
        float    minVal = 0.0f;
        int i0 = istart, j0 = 0, step = 0;

        for (;;) {
            if (j0 == j) {               // my column settled: freeze, mark
                usedf = 1u;
                myrow = i0;
                mshort = minVal;
                vv = -INF_F;
            }

            const float4 p = spt[i0 - 1];          // xyz + u[i0], LDS.128 bcast
            const float dx = p.x - tx, dy = p.y - ty, dz = p.z - tz;
            const float s  = sqrt_approx(fmaf(dx, dx, fmaf(dy, dy, dz * dz)));
            const float cur = fmaxf((minVal - p.w - vv) + s, 0.0f);  // used: +INF
            const unsigned ck = __float_as_uint(cur) | 0x80000000u;
            if (ck < ekey) {             // used cols: INF key never passes
                ekey = ck;
                sway[j] = (short)j0;
            }

            // masked key; one REDUX carries (trunc value | lane), one exact value
            const unsigned kk = ekey | (0u - usedf);
            const unsigned wp = __reduce_min_sync(FULLM, (kk & ~31u) | (unsigned)lane);
            const unsigned we = __reduce_min_sync(FULLM, kk);
            const int buf = step & 1;
            if (lane == 0)
                rbuf[buf][w] = ((unsigned long long)we << 32)
                             | (unsigned)((w << 5) | (int)(wp & 31u));
            __syncthreads();

            // block combine: 4x LDS.128, u64 min (exact value, fuzzy 5-bit tiebreak)
            const ulonglong2* rb = reinterpret_cast<const ulonglong2*>(rbuf[buf]);
            const ulonglong2 a0 = rb[0], a1 = rb[1], a2 = rb[2], a3 = rb[3];
            unsigned long long m0 = a0.x < a0.y ? a0.x : a0.y;
            unsigned long long m1 = a1.x < a1.y ? a1.x : a1.y;
            unsigned long long m2 = a2.x < a2.y ? a2.x : a2.y;
            unsigned long long m3 = a3.x < a3.y ? a3.x : a3.y;
            m0 = m0 < m1 ? m0 : m1;
            m2 = m2 < m3 ? m2 : m3;
            const unsigned long long best = m0 < m2 ? m0 : m2;

            minVal = __uint_as_float(((unsigned)(best >> 32)) & 0x7fffffffu);
            const int j1  = (int)(best & 0xffu) + 1;
            const int i0n = sp[j1];      // doubles as next step's sp[j0]

            if (i0n == 0) {
                __syncthreads();         // all reads of sp/sway/spt.w done
                if (usedf) {
                    const float d = minVal - mshort;
                    v -= d;
                    spt[myrow - 1].w += d;   // distinct rows: no conflict
                }
                if (t == 0) {
                    spt[istart - 1].w += minVal;
                    sp[0] = istart;          // terminus picks up the free row
                    int jj = j1;
                    while (jj) {
                        const int jn = sway[jj];
                        sp[jj] = sp[jn];
                        jj = jn;
                    }
                }
                __syncthreads();
                break;
            }
            j0 = j1;
            i0 = i0n;
            ++step;
        }
    }

    // ---- matched distance for my column (exact sqrt) ----
    const int r = sp[j] - 1;
    const float4 p = spt[r];
    const float dx = p.x - tx, dy = p.y - ty, dz = p.z - tz;
    float md = sqrtf(fmaf(dx, dx, fmaf(dy, dy, dz * dz)));

    #pragma unroll
    for (int o = 16; o > 0; o >>= 1)
        md += __shfl_down_sync(FULLM, md, o);
    if (lane == 0) fsum[w] = md;
    __syncthreads();
    if (t == 0) {
        float s = 0.0f;
        #pragma unroll
        for (int q = 0; q < 8; ++q) s += fsum[q];
        g_batch_sum[b] = s;
    }
}

__global__ void finalize_kernel(float* __restrict__ out)
{
    double s = 0.0;
    #pragma unroll
    for (int b = 0; b < BATCH; ++b) s += (double)g_batch_sum[b];
    out[0] = (float)(s / (double)BATCH);
}

extern "C" void kernel_launch(void* const* d_in, const int* in_sizes, int n_in,
                              void* d_out, int out_size)
{
    const float* pred   = (const float*)d_in[0];
    const float* target = (const float*)d_in[1];
    float* out = (float*)d_out;

    hungarian_kernel<<<BATCH, NT>>>(pred, target);
    finalize_kernel<<<1, 1>>>(out);
}